// round 7
// baseline (speedup 1.0000x reference)
#include <cuda_runtime.h>

#define N_NODES 100000
#define N_EDGES 1000000
#define D 64
#define NEG_SLOPE 0.01f

// Scratch: aggregation buffer (25.6 MB). float4 type -> guaranteed 16B alignment.
__device__ float4 g_agg4[N_NODES * D / 4];
__device__ int    g_idx_is64;   // 1 if edge_index buffer is int64, 0 if int32

// ---------------------------------------------------------------------------
// Kernel 0: detect edge-index dtype (int64 -> odd 32-bit words all zero).
// ---------------------------------------------------------------------------
__global__ void detect_kernel(const int* __restrict__ ei32) {
    __shared__ int any_nonzero;
    if (threadIdx.x == 0) any_nonzero = 0;
    __syncthreads();
    int local = 0;
    for (int i = threadIdx.x; i < 1024; i += blockDim.x)
        local |= (ei32[2 * i + 1] != 0);
    if (local) atomicOr(&any_nonzero, 1);
    __syncthreads();
    if (threadIdx.x == 0) g_idx_is64 = (any_nonzero == 0) ? 1 : 0;
}

// ---------------------------------------------------------------------------
// Kernel 1: agg[i] = (1+eps) * x[i]   (float4 vectorized)
// ---------------------------------------------------------------------------
__global__ void init_kernel(const float4* __restrict__ x4,
                            const float* __restrict__ eps) {
    int i = blockIdx.x * blockDim.x + threadIdx.x;
    const int n4 = N_NODES * D / 4;
    if (i >= n4) return;
    float s = 1.0f + *eps;
    float4 v = x4[i];
    v.x *= s; v.y *= s; v.z *= s; v.w *= s;
    g_agg4[i] = v;
}

// ---------------------------------------------------------------------------
// Kernel 2: scatter-add  agg[dst] += x[src]
// 16 threads/edge, one float4 chunk each via red.global.add.v4.f32.
// ---------------------------------------------------------------------------
__global__ void scatter_kernel(const float4* __restrict__ x4,
                               const void* __restrict__ ei_raw) {
    int t = blockIdx.x * blockDim.x + threadIdx.x;
    int e = t >> 4;
    if (e >= N_EDGES) return;
    int c = t & 15;

    int src, dst;
    if (g_idx_is64) {
        const long long* ei = (const long long*)ei_raw;
        src = (int)__ldg(&ei[e]);
        dst = (int)__ldg(&ei[N_EDGES + e]);
    } else {
        const int* ei = (const int*)ei_raw;
        src = __ldg(&ei[e]);
        dst = __ldg(&ei[N_EDGES + e]);
    }
    if ((unsigned)src >= N_NODES || (unsigned)dst >= N_NODES) return;

    float4 v = __ldg(&x4[src * (D / 4) + c]);
    float4* p = &g_agg4[dst * (D / 4) + c];
    asm volatile("red.global.add.v4.f32 [%0], {%1,%2,%3,%4};"
                 :: "l"(p), "f"(v.x), "f"(v.y), "f"(v.z), "f"(v.w)
                 : "memory");
}

// ---------------------------------------------------------------------------
// Kernel 3: fused 2-layer MLP, 8x4 register tiling.
// Block (16,8) = 128 threads, tile = 64 nodes x 64 cols.
// Thread (tx,ty) computes rows 8*ty..+7, cols 4*tx..+3.
// Per k-step (unroll 4): 12 LDS.128 per 128 lane-FMAs = 1.5 B/FMA-lane
// (was 2.0) -> shared crossbar no longer co-binding with the fma pipe.
// ---------------------------------------------------------------------------
__global__ __launch_bounds__(128) void mlp_kernel(
    const float4* __restrict__ W1, const float* __restrict__ b1,
    const float4* __restrict__ W2, const float* __restrict__ b2,
    float* __restrict__ out) {
    __shared__ float Ws[D * D];      // Ws[k][col], 16 KB
    __shared__ float bs[D];
    __shared__ float h_s[64][D];     // h_s[row][k], 16 KB, reused in place

    const int tx = threadIdx.x;      // 0..15 -> col group (4 cols)
    const int ty = threadIdx.y;      // 0..7  -> row group (8 rows)
    const int tid = ty * 16 + tx;    // 0..127
    const int node0 = blockIdx.x * 64;

    // ---- Stage h tile (float4 global loads, zero-pad tail rows) ----
    const float4 zero4 = make_float4(0.f, 0.f, 0.f, 0.f);
    #pragma unroll
    for (int i = 0; i < 8; i++) {
        int idx = tid + 128 * i;           // 0..1023 float4 slots
        int r  = idx >> 4;                 // row 0..63
        int c4 = idx & 15;                 // float4 col 0..15
        int n = node0 + r;
        float4 v = (n < N_NODES) ? g_agg4[n * 16 + c4] : zero4;
        *reinterpret_cast<float4*>(&h_s[r][c4 * 4]) = v;
    }
    // ---- Stage W1, b1 ----
    #pragma unroll
    for (int i = 0; i < 8; i++) {
        int idx = tid + 128 * i;           // 1024 float4 = 64x64
        reinterpret_cast<float4*>(Ws)[idx] = W1[idx];
    }
    if (tid < D) bs[tid] = b1[tid];
    __syncthreads();

    // ---- Layer 1: 8x4 register tile ----
    float acc[8][4];
    {
        float4 bv = *reinterpret_cast<const float4*>(&bs[4 * tx]);
        #pragma unroll
        for (int j = 0; j < 8; j++) {
            acc[j][0] = bv.x; acc[j][1] = bv.y; acc[j][2] = bv.z; acc[j][3] = bv.w;
        }
    }
    #pragma unroll
    for (int k0 = 0; k0 < D; k0 += 4) {
        float4 wv[4];
        #pragma unroll
        for (int q = 0; q < 4; q++)
            wv[q] = *reinterpret_cast<const float4*>(&Ws[(k0 + q) * D + 4 * tx]);
        #pragma unroll
        for (int j = 0; j < 8; j++) {
            float4 hv = *reinterpret_cast<const float4*>(&h_s[8 * ty + j][k0]);
            acc[j][0] += hv.x * wv[0].x + hv.y * wv[1].x + hv.z * wv[2].x + hv.w * wv[3].x;
            acc[j][1] += hv.x * wv[0].y + hv.y * wv[1].y + hv.z * wv[2].y + hv.w * wv[3].y;
            acc[j][2] += hv.x * wv[0].z + hv.y * wv[1].z + hv.z * wv[2].z + hv.w * wv[3].z;
            acc[j][3] += hv.x * wv[0].w + hv.y * wv[1].w + hv.z * wv[2].w + hv.w * wv[3].w;
        }
    }
    __syncthreads();   // all reads of h_s and Ws complete

    // ---- Activate + write back into h_s; stage W2, b2 ----
    #pragma unroll
    for (int j = 0; j < 8; j++) {
        float4 v;
        v.x = (acc[j][0] >= 0.f) ? acc[j][0] : NEG_SLOPE * acc[j][0];
        v.y = (acc[j][1] >= 0.f) ? acc[j][1] : NEG_SLOPE * acc[j][1];
        v.z = (acc[j][2] >= 0.f) ? acc[j][2] : NEG_SLOPE * acc[j][2];
        v.w = (acc[j][3] >= 0.f) ? acc[j][3] : NEG_SLOPE * acc[j][3];
        *reinterpret_cast<float4*>(&h_s[8 * ty + j][4 * tx]) = v;
    }
    #pragma unroll
    for (int i = 0; i < 8; i++) {
        int idx = tid + 128 * i;
        reinterpret_cast<float4*>(Ws)[idx] = W2[idx];
    }
    if (tid < D) bs[tid] = b2[tid];
    __syncthreads();

    // ---- Layer 2 ----
    {
        float4 bv = *reinterpret_cast<const float4*>(&bs[4 * tx]);
        #pragma unroll
        for (int j = 0; j < 8; j++) {
            acc[j][0] = bv.x; acc[j][1] = bv.y; acc[j][2] = bv.z; acc[j][3] = bv.w;
        }
    }
    #pragma unroll
    for (int k0 = 0; k0 < D; k0 += 4) {
        float4 wv[4];
        #pragma unroll
        for (int q = 0; q < 4; q++)
            wv[q] = *reinterpret_cast<const float4*>(&Ws[(k0 + q) * D + 4 * tx]);
        #pragma unroll
        for (int j = 0; j < 8; j++) {
            float4 hv = *reinterpret_cast<const float4*>(&h_s[8 * ty + j][k0]);
            acc[j][0] += hv.x * wv[0].x + hv.y * wv[1].x + hv.z * wv[2].x + hv.w * wv[3].x;
            acc[j][1] += hv.x * wv[0].y + hv.y * wv[1].y + hv.z * wv[2].y + hv.w * wv[3].y;
            acc[j][2] += hv.x * wv[0].z + hv.y * wv[1].z + hv.z * wv[2].z + hv.w * wv[3].z;
            acc[j][3] += hv.x * wv[0].w + hv.y * wv[1].w + hv.z * wv[2].w + hv.w * wv[3].w;
        }
    }

    // ---- Activate + store out (float4) ----
    #pragma unroll
    for (int j = 0; j < 8; j++) {
        int n = node0 + 8 * ty + j;
        if (n < N_NODES) {
            float4 v;
            v.x = (acc[j][0] >= 0.f) ? acc[j][0] : NEG_SLOPE * acc[j][0];
            v.y = (acc[j][1] >= 0.f) ? acc[j][1] : NEG_SLOPE * acc[j][1];
            v.z = (acc[j][2] >= 0.f) ? acc[j][2] : NEG_SLOPE * acc[j][2];
            v.w = (acc[j][3] >= 0.f) ? acc[j][3] : NEG_SLOPE * acc[j][3];
            *reinterpret_cast<float4*>(&out[n * D + 4 * tx]) = v;
        }
    }
}

// ---------------------------------------------------------------------------
extern "C" void kernel_launch(void* const* d_in, const int* in_sizes, int n_in,
                              void* d_out, int out_size) {
    const float4* x4  = (const float4*)d_in[0];
    const void*   ei  = d_in[1];
    const float*  eps = (const float*)d_in[2];
    const float4* W1  = (const float4*)d_in[3];
    const float*  b1  = (const float*)d_in[4];
    const float4* W2  = (const float4*)d_in[5];
    const float*  b2  = (const float*)d_in[6];
    float*        out = (float*)d_out;

    detect_kernel<<<1, 256>>>((const int*)ei);

    {
        int n4 = N_NODES * D / 4;
        init_kernel<<<(n4 + 255) / 256, 256>>>(x4, eps);
    }
    {
        long long total = (long long)N_EDGES * 16;
        int blocks = (int)((total + 255) / 256);
        scatter_kernel<<<blocks, 256>>>(x4, ei);
    }
    {
        dim3 blk(16, 8);
        mlp_kernel<<<(N_NODES + 63) / 64, blk>>>(W1, b1, W2, b2, out);
    }
}

// round 8
// speedup vs baseline: 1.0169x; 1.0169x over previous
#include <cuda_runtime.h>

#define N_NODES 100000
#define N_EDGES 1000000
#define D 64
#define NEG_SLOPE 0.01f

// Scratch: aggregation buffer (25.6 MB). float4 type -> guaranteed 16B alignment.
__device__ float4 g_agg4[N_NODES * D / 4];
__device__ int    g_idx_is64;   // 1 if edge_index buffer is int64, 0 if int32

// ---------------------------------------------------------------------------
// Kernel 0: detect edge-index dtype (int64 -> odd 32-bit words all zero).
// ---------------------------------------------------------------------------
__global__ void detect_kernel(const int* __restrict__ ei32) {
    __shared__ int any_nonzero;
    if (threadIdx.x == 0) any_nonzero = 0;
    __syncthreads();
    int local = 0;
    for (int i = threadIdx.x; i < 1024; i += blockDim.x)
        local |= (ei32[2 * i + 1] != 0);
    if (local) atomicOr(&any_nonzero, 1);
    __syncthreads();
    if (threadIdx.x == 0) g_idx_is64 = (any_nonzero == 0) ? 1 : 0;
}

// ---------------------------------------------------------------------------
// Kernel 1: agg[i] = (1+eps) * x[i]   (float4 vectorized)
// ---------------------------------------------------------------------------
__global__ void init_kernel(const float4* __restrict__ x4,
                            const float* __restrict__ eps) {
    int i = blockIdx.x * blockDim.x + threadIdx.x;
    const int n4 = N_NODES * D / 4;
    if (i >= n4) return;
    float s = 1.0f + *eps;
    float4 v = x4[i];
    v.x *= s; v.y *= s; v.z *= s; v.w *= s;
    g_agg4[i] = v;
}

// ---------------------------------------------------------------------------
// Kernel 2: scatter-add  agg[dst] += x[src]
// 16 threads/edge, one float4 chunk each via red.global.add.v4.f32.
// ---------------------------------------------------------------------------
__global__ void scatter_kernel(const float4* __restrict__ x4,
                               const void* __restrict__ ei_raw) {
    int t = blockIdx.x * blockDim.x + threadIdx.x;
    int e = t >> 4;
    if (e >= N_EDGES) return;
    int c = t & 15;

    int src, dst;
    if (g_idx_is64) {
        const long long* ei = (const long long*)ei_raw;
        src = (int)__ldg(&ei[e]);
        dst = (int)__ldg(&ei[N_EDGES + e]);
    } else {
        const int* ei = (const int*)ei_raw;
        src = __ldg(&ei[e]);
        dst = __ldg(&ei[N_EDGES + e]);
    }
    if ((unsigned)src >= N_NODES || (unsigned)dst >= N_NODES) return;

    float4 v = __ldg(&x4[src * (D / 4) + c]);
    float4* p = &g_agg4[dst * (D / 4) + c];
    asm volatile("red.global.add.v4.f32 [%0], {%1,%2,%3,%4};"
                 :: "l"(p), "f"(v.x), "f"(v.y), "f"(v.z), "f"(v.w)
                 : "memory");
}

// ---------------------------------------------------------------------------
// Kernel 3: fused 2-layer MLP, 4x4 register tiling.
// Block (16,16) = 256 threads, tile = 64 nodes x 64 cols.
// Weights read directly from global via __ldg (16 KB each, L1-resident,
// shared by all CTAs) -> no smem staging, smem = 16.3 KB/CTA, 4+ CTAs/SM.
// ---------------------------------------------------------------------------
__global__ __launch_bounds__(256, 4) void mlp_kernel(
    const float4* __restrict__ W1, const float4* __restrict__ b1,
    const float4* __restrict__ W2, const float4* __restrict__ b2,
    float* __restrict__ out) {
    __shared__ float h_s[64][D];     // h_s[row][k], 16 KB, reused in place

    const int tx = threadIdx.x;      // 0..15 -> col group (4 cols)
    const int ty = threadIdx.y;      // 0..15 -> row group (4 rows)
    const int tid = ty * 16 + tx;    // 0..255
    const int node0 = blockIdx.x * 64;

    // ---- Stage h tile (float4 global loads, zero-pad tail rows) ----
    const float4 zero4 = make_float4(0.f, 0.f, 0.f, 0.f);
    #pragma unroll
    for (int i = 0; i < 4; i++) {
        int idx = tid + 256 * i;           // 0..1023 float4 slots
        int r  = idx >> 4;                 // row 0..63
        int c4 = idx & 15;                 // float4 col 0..15
        int n = node0 + r;
        float4 v = (n < N_NODES) ? g_agg4[n * 16 + c4] : zero4;
        *reinterpret_cast<float4*>(&h_s[r][c4 * 4]) = v;
    }
    __syncthreads();

    // ---- Layer 1: 4x4 register tile, W1 via LDG (L1-hot) ----
    float acc[4][4];
    {
        float4 bv = __ldg(&b1[tx]);
        #pragma unroll
        for (int j = 0; j < 4; j++) {
            acc[j][0] = bv.x; acc[j][1] = bv.y; acc[j][2] = bv.z; acc[j][3] = bv.w;
        }
    }
    #pragma unroll
    for (int k0 = 0; k0 < D; k0 += 4) {
        float4 hv[4], wv[4];
        #pragma unroll
        for (int j = 0; j < 4; j++)
            hv[j] = *reinterpret_cast<const float4*>(&h_s[4 * ty + j][k0]);
        #pragma unroll
        for (int q = 0; q < 4; q++)
            wv[q] = __ldg(&W1[(k0 + q) * 16 + tx]);
        #pragma unroll
        for (int j = 0; j < 4; j++) {
            const float hk0 = hv[j].x, hk1 = hv[j].y, hk2 = hv[j].z, hk3 = hv[j].w;
            acc[j][0] += hk0 * wv[0].x + hk1 * wv[1].x + hk2 * wv[2].x + hk3 * wv[3].x;
            acc[j][1] += hk0 * wv[0].y + hk1 * wv[1].y + hk2 * wv[2].y + hk3 * wv[3].y;
            acc[j][2] += hk0 * wv[0].z + hk1 * wv[1].z + hk2 * wv[2].z + hk3 * wv[3].z;
            acc[j][3] += hk0 * wv[0].w + hk1 * wv[1].w + hk2 * wv[2].w + hk3 * wv[3].w;
        }
    }
    __syncthreads();   // all reads of h_s complete

    // ---- Activate + write back into h_s ----
    #pragma unroll
    for (int j = 0; j < 4; j++) {
        float4 v;
        v.x = (acc[j][0] >= 0.f) ? acc[j][0] : NEG_SLOPE * acc[j][0];
        v.y = (acc[j][1] >= 0.f) ? acc[j][1] : NEG_SLOPE * acc[j][1];
        v.z = (acc[j][2] >= 0.f) ? acc[j][2] : NEG_SLOPE * acc[j][2];
        v.w = (acc[j][3] >= 0.f) ? acc[j][3] : NEG_SLOPE * acc[j][3];
        *reinterpret_cast<float4*>(&h_s[4 * ty + j][4 * tx]) = v;
    }
    __syncthreads();

    // ---- Layer 2: W2 via LDG ----
    {
        float4 bv = __ldg(&b2[tx]);
        #pragma unroll
        for (int j = 0; j < 4; j++) {
            acc[j][0] = bv.x; acc[j][1] = bv.y; acc[j][2] = bv.z; acc[j][3] = bv.w;
        }
    }
    #pragma unroll
    for (int k0 = 0; k0 < D; k0 += 4) {
        float4 hv[4], wv[4];
        #pragma unroll
        for (int j = 0; j < 4; j++)
            hv[j] = *reinterpret_cast<const float4*>(&h_s[4 * ty + j][k0]);
        #pragma unroll
        for (int q = 0; q < 4; q++)
            wv[q] = __ldg(&W2[(k0 + q) * 16 + tx]);
        #pragma unroll
        for (int j = 0; j < 4; j++) {
            const float hk0 = hv[j].x, hk1 = hv[j].y, hk2 = hv[j].z, hk3 = hv[j].w;
            acc[j][0] += hk0 * wv[0].x + hk1 * wv[1].x + hk2 * wv[2].x + hk3 * wv[3].x;
            acc[j][1] += hk0 * wv[0].y + hk1 * wv[1].y + hk2 * wv[2].y + hk3 * wv[3].y;
            acc[j][2] += hk0 * wv[0].z + hk1 * wv[1].z + hk2 * wv[2].z + hk3 * wv[3].z;
            acc[j][3] += hk0 * wv[0].w + hk1 * wv[1].w + hk2 * wv[2].w + hk3 * wv[3].w;
        }
    }

    // ---- Activate + store out (float4) ----
    #pragma unroll
    for (int j = 0; j < 4; j++) {
        int n = node0 + 4 * ty + j;
        if (n < N_NODES) {
            float4 v;
            v.x = (acc[j][0] >= 0.f) ? acc[j][0] : NEG_SLOPE * acc[j][0];
            v.y = (acc[j][1] >= 0.f) ? acc[j][1] : NEG_SLOPE * acc[j][1];
            v.z = (acc[j][2] >= 0.f) ? acc[j][2] : NEG_SLOPE * acc[j][2];
            v.w = (acc[j][3] >= 0.f) ? acc[j][3] : NEG_SLOPE * acc[j][3];
            *reinterpret_cast<float4*>(&out[n * D + 4 * tx]) = v;
        }
    }
}

// ---------------------------------------------------------------------------
extern "C" void kernel_launch(void* const* d_in, const int* in_sizes, int n_in,
                              void* d_out, int out_size) {
    const float4* x4  = (const float4*)d_in[0];
    const void*   ei  = d_in[1];
    const float*  eps = (const float*)d_in[2];
    const float4* W1  = (const float4*)d_in[3];
    const float4* b1  = (const float4*)d_in[4];
    const float4* W2  = (const float4*)d_in[5];
    const float4* b2  = (const float4*)d_in[6];
    float*        out = (float*)d_out;

    detect_kernel<<<1, 256>>>((const int*)ei);

    {
        int n4 = N_NODES * D / 4;
        init_kernel<<<(n4 + 255) / 256, 256>>>(x4, eps);
    }
    {
        long long total = (long long)N_EDGES * 16;
        int blocks = (int)((total + 255) / 256);
        scatter_kernel<<<blocks, 256>>>(x4, ei);
    }
    {
        dim3 blk(16, 16);
        mlp_kernel<<<(N_NODES + 63) / 64, blk>>>(W1, b1, W2, b2, out);
    }
}

// round 9
// speedup vs baseline: 1.2448x; 1.2241x over previous
#include <cuda_runtime.h>
#include <cstdint>

#define N_NODES 100000
#define N_EDGES 1000000
#define D 64
#define NEG_SLOPE 0.01f

// Scratch: aggregation buffer (25.6 MB). float4 type -> guaranteed 16B alignment.
__device__ float4 g_agg4[N_NODES * D / 4];
__device__ int    g_idx_is64;   // 1 if edge_index buffer is int64, 0 if int32

// ---------------------------------------------------------------------------
// Kernel 0: detect edge-index dtype (int64 -> odd 32-bit words all zero).
// ---------------------------------------------------------------------------
__global__ void detect_kernel(const int* __restrict__ ei32) {
    __shared__ int any_nonzero;
    if (threadIdx.x == 0) any_nonzero = 0;
    __syncthreads();
    int local = 0;
    for (int i = threadIdx.x; i < 1024; i += blockDim.x)
        local |= (ei32[2 * i + 1] != 0);
    if (local) atomicOr(&any_nonzero, 1);
    __syncthreads();
    if (threadIdx.x == 0) g_idx_is64 = (any_nonzero == 0) ? 1 : 0;
}

// ---------------------------------------------------------------------------
// Kernel 1: agg[i] = (1+eps) * x[i]   (float4 vectorized)
// ---------------------------------------------------------------------------
__global__ void init_kernel(const float4* __restrict__ x4,
                            const float* __restrict__ eps) {
    int i = blockIdx.x * blockDim.x + threadIdx.x;
    const int n4 = N_NODES * D / 4;
    if (i >= n4) return;
    float s = 1.0f + *eps;
    float4 v = x4[i];
    v.x *= s; v.y *= s; v.z *= s; v.w *= s;
    g_agg4[i] = v;
}

// ---------------------------------------------------------------------------
// Kernel 2: scatter-add  agg[dst] += x[src]
// 16 threads/edge, one float4 chunk each via red.global.add.v4.f32.
// ---------------------------------------------------------------------------
__global__ void scatter_kernel(const float4* __restrict__ x4,
                               const void* __restrict__ ei_raw) {
    int t = blockIdx.x * blockDim.x + threadIdx.x;
    int e = t >> 4;
    if (e >= N_EDGES) return;
    int c = t & 15;

    int src, dst;
    if (g_idx_is64) {
        const long long* ei = (const long long*)ei_raw;
        src = (int)__ldg(&ei[e]);
        dst = (int)__ldg(&ei[N_EDGES + e]);
    } else {
        const int* ei = (const int*)ei_raw;
        src = __ldg(&ei[e]);
        dst = __ldg(&ei[N_EDGES + e]);
    }
    if ((unsigned)src >= N_NODES || (unsigned)dst >= N_NODES) return;

    float4 v = __ldg(&x4[src * (D / 4) + c]);
    float4* p = &g_agg4[dst * (D / 4) + c];
    asm volatile("red.global.add.v4.f32 [%0], {%1,%2,%3,%4};"
                 :: "l"(p), "f"(v.x), "f"(v.y), "f"(v.z), "f"(v.w)
                 : "memory");
}

// ---------------------------------------------------------------------------
// Kernel 3: tf32 tensor-core MLP.
// Block = 128 threads (4 warps). Tile = 64 nodes x 64 cols.
// Warp w computes rows 16w..16w+15 via mma.sync.m16n8k8 (tf32, fp32 accum).
// h_s / w_s hold tf32-pre-rounded values, XOR-swizzled in float4 units
// (c4 ^= row&7) -> conflict-free A and B fragment LDS.
// ---------------------------------------------------------------------------
__device__ __forceinline__ float f2tf32(float x) {
    uint32_t u;
    asm("cvt.rna.tf32.f32 %0, %1;" : "=r"(u) : "f"(x));
    return __uint_as_float(u);
}

__device__ __forceinline__ void mma_tf32(
    float& c0, float& c1, float& c2, float& c3,
    uint32_t a0, uint32_t a1, uint32_t a2, uint32_t a3,
    uint32_t b0, uint32_t b1) {
    asm volatile(
        "mma.sync.aligned.m16n8k8.row.col.f32.tf32.tf32.f32 "
        "{%0,%1,%2,%3}, {%4,%5,%6,%7}, {%8,%9}, {%0,%1,%2,%3};\n"
        : "+f"(c0), "+f"(c1), "+f"(c2), "+f"(c3)
        : "r"(a0), "r"(a1), "r"(a2), "r"(a3), "r"(b0), "r"(b1));
}

// swizzled float index for element (r, col) of a [64][64] tile:
//   float4 index = r*16 + ((col>>2) ^ (r&7)), plus col&3 within.
__device__ __forceinline__ int swz(int r, int col) {
    return (r * 16 + (((col >> 2) ^ (r & 7)))) * 4 + (col & 3);
}

__global__ __launch_bounds__(128) void mlp_kernel(
    const float4* __restrict__ W1, const float* __restrict__ b1,
    const float4* __restrict__ W2, const float* __restrict__ b2,
    float* __restrict__ out) {
    __shared__ float h_s[64 * 64];   // A operand (tf32 bits), swizzled
    __shared__ float w_s[64 * 64];   // B operand (tf32 bits), swizzled

    const int tid  = threadIdx.x;    // 0..127
    const int w    = tid >> 5;       // warp 0..3
    const int lane = tid & 31;
    const int gid  = lane >> 2;      // group id 0..7
    const int tig  = lane & 3;       // thread-in-group 0..3
    const int node0 = blockIdx.x * 64;

    // ---- Stage h tile (tf32-rounded, swizzled) ----
    const float4 zero4 = make_float4(0.f, 0.f, 0.f, 0.f);
    #pragma unroll
    for (int it = 0; it < 8; it++) {
        int idx = tid + 128 * it;          // 0..1023 float4 slots
        int r  = idx >> 4;
        int c4 = idx & 15;
        int n = node0 + r;
        float4 v = (n < N_NODES) ? g_agg4[n * 16 + c4] : zero4;
        v.x = f2tf32(v.x); v.y = f2tf32(v.y); v.z = f2tf32(v.z); v.w = f2tf32(v.w);
        reinterpret_cast<float4*>(h_s)[r * 16 + (c4 ^ (r & 7))] = v;
    }
    // ---- Stage W1 (tf32-rounded, swizzled; w_s[k][n] = W1[k][n]) ----
    #pragma unroll
    for (int it = 0; it < 8; it++) {
        int idx = tid + 128 * it;
        int k  = idx >> 4;
        int c4 = idx & 15;
        float4 v = W1[idx];
        v.x = f2tf32(v.x); v.y = f2tf32(v.y); v.z = f2tf32(v.z); v.w = f2tf32(v.w);
        reinterpret_cast<float4*>(w_s)[k * 16 + (c4 ^ (k & 7))] = v;
    }
    __syncthreads();

    // ================= Layer 1 =================
    float acc[8][4];
    #pragma unroll
    for (int nc = 0; nc < 8; nc++) {
        float blo = __ldg(&b1[8 * nc + 2 * tig]);
        float bhi = __ldg(&b1[8 * nc + 2 * tig + 1]);
        acc[nc][0] = blo; acc[nc][1] = bhi; acc[nc][2] = blo; acc[nc][3] = bhi;
    }
    #pragma unroll
    for (int kc = 0; kc < 8; kc++) {
        int r0 = 16 * w + gid, r1 = r0 + 8;
        uint32_t a0 = __float_as_uint(h_s[swz(r0, 8 * kc + tig)]);
        uint32_t a1 = __float_as_uint(h_s[swz(r1, 8 * kc + tig)]);
        uint32_t a2 = __float_as_uint(h_s[swz(r0, 8 * kc + tig + 4)]);
        uint32_t a3 = __float_as_uint(h_s[swz(r1, 8 * kc + tig + 4)]);
        #pragma unroll
        for (int nc = 0; nc < 8; nc++) {
            uint32_t b0 = __float_as_uint(w_s[swz(8 * kc + tig,     8 * nc + gid)]);
            uint32_t bb = __float_as_uint(w_s[swz(8 * kc + tig + 4, 8 * nc + gid)]);
            mma_tf32(acc[nc][0], acc[nc][1], acc[nc][2], acc[nc][3],
                     a0, a1, a2, a3, b0, bb);
        }
    }
    __syncthreads();   // all h_s / w_s reads done

    // ---- Activate + write layer-1 output back into h_s (tf32, swizzled) ----
    #pragma unroll
    for (int nc = 0; nc < 8; nc++) {
        int col = 8 * nc + 2 * tig;
        int r0 = 16 * w + gid, r1 = r0 + 8;
        float v0 = acc[nc][0], v1 = acc[nc][1], v2 = acc[nc][2], v3 = acc[nc][3];
        v0 = (v0 >= 0.f) ? v0 : NEG_SLOPE * v0;
        v1 = (v1 >= 0.f) ? v1 : NEG_SLOPE * v1;
        v2 = (v2 >= 0.f) ? v2 : NEG_SLOPE * v2;
        v3 = (v3 >= 0.f) ? v3 : NEG_SLOPE * v3;
        *reinterpret_cast<float2*>(&h_s[swz(r0, col)]) =
            make_float2(f2tf32(v0), f2tf32(v1));
        *reinterpret_cast<float2*>(&h_s[swz(r1, col)]) =
            make_float2(f2tf32(v2), f2tf32(v3));
    }
    // ---- Stage W2 ----
    #pragma unroll
    for (int it = 0; it < 8; it++) {
        int idx = tid + 128 * it;
        int k  = idx >> 4;
        int c4 = idx & 15;
        float4 v = W2[idx];
        v.x = f2tf32(v.x); v.y = f2tf32(v.y); v.z = f2tf32(v.z); v.w = f2tf32(v.w);
        reinterpret_cast<float4*>(w_s)[k * 16 + (c4 ^ (k & 7))] = v;
    }
    __syncthreads();

    // ================= Layer 2 =================
    #pragma unroll
    for (int nc = 0; nc < 8; nc++) {
        float blo = __ldg(&b2[8 * nc + 2 * tig]);
        float bhi = __ldg(&b2[8 * nc + 2 * tig + 1]);
        acc[nc][0] = blo; acc[nc][1] = bhi; acc[nc][2] = blo; acc[nc][3] = bhi;
    }
    #pragma unroll
    for (int kc = 0; kc < 8; kc++) {
        int r0 = 16 * w + gid, r1 = r0 + 8;
        uint32_t a0 = __float_as_uint(h_s[swz(r0, 8 * kc + tig)]);
        uint32_t a1 = __float_as_uint(h_s[swz(r1, 8 * kc + tig)]);
        uint32_t a2 = __float_as_uint(h_s[swz(r0, 8 * kc + tig + 4)]);
        uint32_t a3 = __float_as_uint(h_s[swz(r1, 8 * kc + tig + 4)]);
        #pragma unroll
        for (int nc = 0; nc < 8; nc++) {
            uint32_t b0 = __float_as_uint(w_s[swz(8 * kc + tig,     8 * nc + gid)]);
            uint32_t bb = __float_as_uint(w_s[swz(8 * kc + tig + 4, 8 * nc + gid)]);
            mma_tf32(acc[nc][0], acc[nc][1], acc[nc][2], acc[nc][3],
                     a0, a1, a2, a3, b0, bb);
        }
    }

    // ---- Activate + store out (float2 per row-group) ----
    #pragma unroll
    for (int nc = 0; nc < 8; nc++) {
        int col = 8 * nc + 2 * tig;
        int r0 = 16 * w + gid, r1 = r0 + 8;
        float v0 = acc[nc][0], v1 = acc[nc][1], v2 = acc[nc][2], v3 = acc[nc][3];
        v0 = (v0 >= 0.f) ? v0 : NEG_SLOPE * v0;
        v1 = (v1 >= 0.f) ? v1 : NEG_SLOPE * v1;
        v2 = (v2 >= 0.f) ? v2 : NEG_SLOPE * v2;
        v3 = (v3 >= 0.f) ? v3 : NEG_SLOPE * v3;
        int n0 = node0 + r0, n1 = node0 + r1;
        if (n0 < N_NODES)
            *reinterpret_cast<float2*>(&out[n0 * D + col]) = make_float2(v0, v1);
        if (n1 < N_NODES)
            *reinterpret_cast<float2*>(&out[n1 * D + col]) = make_float2(v2, v3);
    }
}

// ---------------------------------------------------------------------------
extern "C" void kernel_launch(void* const* d_in, const int* in_sizes, int n_in,
                              void* d_out, int out_size) {
    const float4* x4  = (const float4*)d_in[0];
    const void*   ei  = d_in[1];
    const float*  eps = (const float*)d_in[2];
    const float4* W1  = (const float4*)d_in[3];
    const float*  b1  = (const float*)d_in[4];
    const float4* W2  = (const float4*)d_in[5];
    const float*  b2  = (const float*)d_in[6];
    float*        out = (float*)d_out;

    detect_kernel<<<1, 256>>>((const int*)ei);

    {
        int n4 = N_NODES * D / 4;
        init_kernel<<<(n4 + 255) / 256, 256>>>(x4, eps);
    }
    {
        long long total = (long long)N_EDGES * 16;
        int blocks = (int)((total + 255) / 256);
        scatter_kernel<<<blocks, 256>>>(x4, ei);
    }
    {
        mlp_kernel<<<(N_NODES + 63) / 64, 128>>>(W1, b1, W2, b2, out);
    }
}

// round 10
// speedup vs baseline: 1.4587x; 1.1718x over previous
#include <cuda_runtime.h>
#include <cstdint>

#define N_NODES 100000
#define N_EDGES 1000000
#define D 64
#define NEG_SLOPE 0.01f
#define NB_H 391           // ceil(N_NODES / 256)

// Scratch (static __device__, allowed): agg + CSR arrays.
__device__ float4 g_agg4[N_NODES * D / 4];
__device__ int    g_idx_is64;
__device__ int    g_hist[N_NODES];     // per-dst degree
__device__ int    g_off[N_NODES];      // CSR start offsets
__device__ int    g_cur[N_NODES];      // fill cursors
__device__ int    g_srcs[N_EDGES];     // src ids bucketed by dst
__device__ int    g_part[512];         // block partial sums for scan

// ---------------------------------------------------------------------------
// Kernel 0: detect edge-index dtype (int64 -> odd 32-bit words all zero).
// ---------------------------------------------------------------------------
__global__ void detect_kernel(const int* __restrict__ ei32) {
    __shared__ int any_nonzero;
    if (threadIdx.x == 0) any_nonzero = 0;
    __syncthreads();
    int local = 0;
    for (int i = threadIdx.x; i < 1024; i += blockDim.x)
        local |= (ei32[2 * i + 1] != 0);
    if (local) atomicOr(&any_nonzero, 1);
    __syncthreads();
    if (threadIdx.x == 0) g_idx_is64 = (any_nonzero == 0) ? 1 : 0;
}

__device__ __forceinline__ int load_idx(const void* p, int i, int is64) {
    return is64 ? (int)__ldg(&((const long long*)p)[i])
                : __ldg(&((const int*)p)[i]);
}

// ---------------------------------------------------------------------------
// CSR build: zero -> hist -> partial -> scan_small -> add_offsets -> fill
// ---------------------------------------------------------------------------
__global__ void zero_hist_kernel() {
    int i = blockIdx.x * blockDim.x + threadIdx.x;
    if (i < N_NODES) g_hist[i] = 0;
}

__global__ void hist_kernel(const void* __restrict__ ei_raw) {
    int e = blockIdx.x * blockDim.x + threadIdx.x;
    if (e >= N_EDGES) return;
    int is64 = g_idx_is64;
    int dst = load_idx(ei_raw, N_EDGES + e, is64);
    if ((unsigned)dst < N_NODES) atomicAdd(&g_hist[dst], 1);
}

__global__ void partial_kernel() {
    __shared__ int s[256];
    int i = blockIdx.x * 256 + threadIdx.x;
    s[threadIdx.x] = (i < N_NODES) ? g_hist[i] : 0;
    __syncthreads();
    for (int d = 128; d > 0; d >>= 1) {
        if (threadIdx.x < d) s[threadIdx.x] += s[threadIdx.x + d];
        __syncthreads();
    }
    if (threadIdx.x == 0) g_part[blockIdx.x] = s[0];
}

__global__ void scan_small_kernel() {
    // one block, 512 threads: exclusive scan of g_part[0..NB_H)
    __shared__ int s[512];
    int t = threadIdx.x;
    int v = (t < NB_H) ? g_part[t] : 0;
    s[t] = v;
    __syncthreads();
    for (int d = 1; d < 512; d <<= 1) {
        int u = (t >= d) ? s[t - d] : 0;
        __syncthreads();
        s[t] += u;
        __syncthreads();
    }
    if (t < NB_H) g_part[t] = s[t] - v;   // exclusive
}

__global__ void add_offsets_kernel() {
    __shared__ int s[256];
    int t = threadIdx.x;
    int i = blockIdx.x * 256 + t;
    int v = (i < N_NODES) ? g_hist[i] : 0;
    s[t] = v;
    __syncthreads();
    for (int d = 1; d < 256; d <<= 1) {
        int u = (t >= d) ? s[t - d] : 0;
        __syncthreads();
        s[t] += u;
        __syncthreads();
    }
    if (i < N_NODES) {
        int off = g_part[blockIdx.x] + s[t] - v;   // exclusive within block
        g_off[i] = off;
        g_cur[i] = off;
    }
}

__global__ void fill_kernel(const void* __restrict__ ei_raw) {
    int e = blockIdx.x * blockDim.x + threadIdx.x;
    if (e >= N_EDGES) return;
    int is64 = g_idx_is64;
    int src = load_idx(ei_raw, e, is64);
    int dst = load_idx(ei_raw, N_EDGES + e, is64);
    if ((unsigned)src >= N_NODES || (unsigned)dst >= N_NODES) return;
    int pos = atomicAdd(&g_cur[dst], 1);
    g_srcs[pos] = src;
}

// ---------------------------------------------------------------------------
// Gather: agg[n] = (1+eps)*x[n] + sum_{j in CSR(n)} x[srcs[j]]
// 16 threads per node; each lane owns one float4 chunk. Per edge the 16-lane
// group reads one contiguous 256B row of x (coalesced). One write per chunk.
// ---------------------------------------------------------------------------
__global__ void gather_kernel(const float4* __restrict__ x4,
                              const float* __restrict__ eps) {
    int t = blockIdx.x * blockDim.x + threadIdx.x;
    int node = t >> 4;
    if (node >= N_NODES) return;
    int c = t & 15;

    int beg = __ldg(&g_off[node]);
    int end = beg + __ldg(&g_hist[node]);

    float4 acc = make_float4(0.f, 0.f, 0.f, 0.f);
    for (int j = beg; j < end; j++) {
        int s = g_srcs[j];
        float4 v = __ldg(&x4[s * 16 + c]);
        acc.x += v.x; acc.y += v.y; acc.z += v.z; acc.w += v.w;
    }
    float sc = 1.0f + *eps;
    float4 xs = __ldg(&x4[node * 16 + c]);
    acc.x += sc * xs.x; acc.y += sc * xs.y;
    acc.z += sc * xs.z; acc.w += sc * xs.w;
    g_agg4[node * 16 + c] = acc;
}

// ---------------------------------------------------------------------------
// Kernel: tf32 tensor-core MLP (unchanged from R9 winner).
// ---------------------------------------------------------------------------
__device__ __forceinline__ float f2tf32(float x) {
    uint32_t u;
    asm("cvt.rna.tf32.f32 %0, %1;" : "=r"(u) : "f"(x));
    return __uint_as_float(u);
}

__device__ __forceinline__ void mma_tf32(
    float& c0, float& c1, float& c2, float& c3,
    uint32_t a0, uint32_t a1, uint32_t a2, uint32_t a3,
    uint32_t b0, uint32_t b1) {
    asm volatile(
        "mma.sync.aligned.m16n8k8.row.col.f32.tf32.tf32.f32 "
        "{%0,%1,%2,%3}, {%4,%5,%6,%7}, {%8,%9}, {%0,%1,%2,%3};\n"
        : "+f"(c0), "+f"(c1), "+f"(c2), "+f"(c3)
        : "r"(a0), "r"(a1), "r"(a2), "r"(a3), "r"(b0), "r"(b1));
}

__device__ __forceinline__ int swz(int r, int col) {
    return (r * 16 + (((col >> 2) ^ (r & 7)))) * 4 + (col & 3);
}

__global__ __launch_bounds__(128) void mlp_kernel(
    const float4* __restrict__ W1, const float* __restrict__ b1,
    const float4* __restrict__ W2, const float* __restrict__ b2,
    float* __restrict__ out) {
    __shared__ float h_s[64 * 64];
    __shared__ float w_s[64 * 64];

    const int tid  = threadIdx.x;
    const int w    = tid >> 5;
    const int lane = tid & 31;
    const int gid  = lane >> 2;
    const int tig  = lane & 3;
    const int node0 = blockIdx.x * 64;

    const float4 zero4 = make_float4(0.f, 0.f, 0.f, 0.f);
    #pragma unroll
    for (int it = 0; it < 8; it++) {
        int idx = tid + 128 * it;
        int r  = idx >> 4;
        int c4 = idx & 15;
        int n = node0 + r;
        float4 v = (n < N_NODES) ? g_agg4[n * 16 + c4] : zero4;
        v.x = f2tf32(v.x); v.y = f2tf32(v.y); v.z = f2tf32(v.z); v.w = f2tf32(v.w);
        reinterpret_cast<float4*>(h_s)[r * 16 + (c4 ^ (r & 7))] = v;
    }
    #pragma unroll
    for (int it = 0; it < 8; it++) {
        int idx = tid + 128 * it;
        int k  = idx >> 4;
        int c4 = idx & 15;
        float4 v = W1[idx];
        v.x = f2tf32(v.x); v.y = f2tf32(v.y); v.z = f2tf32(v.z); v.w = f2tf32(v.w);
        reinterpret_cast<float4*>(w_s)[k * 16 + (c4 ^ (k & 7))] = v;
    }
    __syncthreads();

    // ================= Layer 1 =================
    float acc[8][4];
    #pragma unroll
    for (int nc = 0; nc < 8; nc++) {
        float blo = __ldg(&b1[8 * nc + 2 * tig]);
        float bhi = __ldg(&b1[8 * nc + 2 * tig + 1]);
        acc[nc][0] = blo; acc[nc][1] = bhi; acc[nc][2] = blo; acc[nc][3] = bhi;
    }
    #pragma unroll
    for (int kc = 0; kc < 8; kc++) {
        int r0 = 16 * w + gid, r1 = r0 + 8;
        uint32_t a0 = __float_as_uint(h_s[swz(r0, 8 * kc + tig)]);
        uint32_t a1 = __float_as_uint(h_s[swz(r1, 8 * kc + tig)]);
        uint32_t a2 = __float_as_uint(h_s[swz(r0, 8 * kc + tig + 4)]);
        uint32_t a3 = __float_as_uint(h_s[swz(r1, 8 * kc + tig + 4)]);
        #pragma unroll
        for (int nc = 0; nc < 8; nc++) {
            uint32_t b0 = __float_as_uint(w_s[swz(8 * kc + tig,     8 * nc + gid)]);
            uint32_t bb = __float_as_uint(w_s[swz(8 * kc + tig + 4, 8 * nc + gid)]);
            mma_tf32(acc[nc][0], acc[nc][1], acc[nc][2], acc[nc][3],
                     a0, a1, a2, a3, b0, bb);
        }
    }
    __syncthreads();

    #pragma unroll
    for (int nc = 0; nc < 8; nc++) {
        int col = 8 * nc + 2 * tig;
        int r0 = 16 * w + gid, r1 = r0 + 8;
        float v0 = acc[nc][0], v1 = acc[nc][1], v2 = acc[nc][2], v3 = acc[nc][3];
        v0 = (v0 >= 0.f) ? v0 : NEG_SLOPE * v0;
        v1 = (v1 >= 0.f) ? v1 : NEG_SLOPE * v1;
        v2 = (v2 >= 0.f) ? v2 : NEG_SLOPE * v2;
        v3 = (v3 >= 0.f) ? v3 : NEG_SLOPE * v3;
        *reinterpret_cast<float2*>(&h_s[swz(r0, col)]) =
            make_float2(f2tf32(v0), f2tf32(v1));
        *reinterpret_cast<float2*>(&h_s[swz(r1, col)]) =
            make_float2(f2tf32(v2), f2tf32(v3));
    }
    #pragma unroll
    for (int it = 0; it < 8; it++) {
        int idx = tid + 128 * it;
        int k  = idx >> 4;
        int c4 = idx & 15;
        float4 v = W2[idx];
        v.x = f2tf32(v.x); v.y = f2tf32(v.y); v.z = f2tf32(v.z); v.w = f2tf32(v.w);
        reinterpret_cast<float4*>(w_s)[k * 16 + (c4 ^ (k & 7))] = v;
    }
    __syncthreads();

    // ================= Layer 2 =================
    #pragma unroll
    for (int nc = 0; nc < 8; nc++) {
        float blo = __ldg(&b2[8 * nc + 2 * tig]);
        float bhi = __ldg(&b2[8 * nc + 2 * tig + 1]);
        acc[nc][0] = blo; acc[nc][1] = bhi; acc[nc][2] = blo; acc[nc][3] = bhi;
    }
    #pragma unroll
    for (int kc = 0; kc < 8; kc++) {
        int r0 = 16 * w + gid, r1 = r0 + 8;
        uint32_t a0 = __float_as_uint(h_s[swz(r0, 8 * kc + tig)]);
        uint32_t a1 = __float_as_uint(h_s[swz(r1, 8 * kc + tig)]);
        uint32_t a2 = __float_as_uint(h_s[swz(r0, 8 * kc + tig + 4)]);
        uint32_t a3 = __float_as_uint(h_s[swz(r1, 8 * kc + tig + 4)]);
        #pragma unroll
        for (int nc = 0; nc < 8; nc++) {
            uint32_t b0 = __float_as_uint(w_s[swz(8 * kc + tig,     8 * nc + gid)]);
            uint32_t bb = __float_as_uint(w_s[swz(8 * kc + tig + 4, 8 * nc + gid)]);
            mma_tf32(acc[nc][0], acc[nc][1], acc[nc][2], acc[nc][3],
                     a0, a1, a2, a3, b0, bb);
        }
    }

    #pragma unroll
    for (int nc = 0; nc < 8; nc++) {
        int col = 8 * nc + 2 * tig;
        int r0 = 16 * w + gid, r1 = r0 + 8;
        float v0 = acc[nc][0], v1 = acc[nc][1], v2 = acc[nc][2], v3 = acc[nc][3];
        v0 = (v0 >= 0.f) ? v0 : NEG_SLOPE * v0;
        v1 = (v1 >= 0.f) ? v1 : NEG_SLOPE * v1;
        v2 = (v2 >= 0.f) ? v2 : NEG_SLOPE * v2;
        v3 = (v3 >= 0.f) ? v3 : NEG_SLOPE * v3;
        int n0 = node0 + r0, n1 = node0 + r1;
        if (n0 < N_NODES)
            *reinterpret_cast<float2*>(&out[n0 * D + col]) = make_float2(v0, v1);
        if (n1 < N_NODES)
            *reinterpret_cast<float2*>(&out[n1 * D + col]) = make_float2(v2, v3);
    }
}

// ---------------------------------------------------------------------------
extern "C" void kernel_launch(void* const* d_in, const int* in_sizes, int n_in,
                              void* d_out, int out_size) {
    const float4* x4  = (const float4*)d_in[0];
    const void*   ei  = d_in[1];
    const float*  eps = (const float*)d_in[2];
    const float4* W1  = (const float4*)d_in[3];
    const float*  b1  = (const float*)d_in[4];
    const float4* W2  = (const float4*)d_in[5];
    const float*  b2  = (const float*)d_in[6];
    float*        out = (float*)d_out;

    detect_kernel<<<1, 256>>>((const int*)ei);

    // --- CSR build ---
    zero_hist_kernel<<<NB_H, 256>>>();
    hist_kernel<<<(N_EDGES + 255) / 256, 256>>>(ei);
    partial_kernel<<<NB_H, 256>>>();
    scan_small_kernel<<<1, 512>>>();
    add_offsets_kernel<<<NB_H, 256>>>();
    fill_kernel<<<(N_EDGES + 255) / 256, 256>>>(ei);

    // --- Gather (fused with (1+eps)*x self term) ---
    {
        long long total = (long long)N_NODES * 16;
        int blocks = (int)((total + 255) / 256);
        gather_kernel<<<blocks, 256>>>(x4, eps);
    }
    // --- MLP ---
    mlp_kernel<<<(N_NODES + 63) / 64, 128>>>(W1, b1, W2, b2, out);
}